// round 14
// baseline (speedup 1.0000x reference)
#include <cuda_runtime.h>
#include <cstdint>

#define Bk 128
#define Sk 128
#define Ek 256
#define Dk 512
#define Kk 16
#define Lk 1906
#define Rk 2033
#define Tk 127
#define TINYF 1.17549435e-38f

// smem layout (float offsets)
#define OFF_BUFA  0        // 32x260
#define OFF_BUFB  8320     // 32x260
#define OFF_BUFC  16640    // 32x260
#define OFF_WA    24960    // 256e x 8dp float2 = 4096
#define OFF_WBI   29056    // 8dp x 514 float2 = 8224
#define OFF_WBH   37280
#define OFF_SE    45504    // 16x256 = 4096
#define OFF_WMK   49600    // 768
#define OFF_WTM   50368    // 512
#define OFF_WTE   50880    // 256
#define OFF_BTE   51136    // 256
#define OFF_BEL   51392    // 512
#define OFF_BIH   51904    // 512
#define OFF_BHH   52416    // 512
#define OFF_BT    52928    // 4: b_time, b_mk, last_t_my
#define OFF_SLT   52932    // 32
#define OFF_SLM   52964    // 32
#define OFF_CS    52996    // red16 redv16 ri16 neigh16 score16 redp12 ripre12
#define OFF_CMB   53100    // 256 ULL (8B aligned: even)
#define OFF_SP    53612    // prob[1906]
#define SM_FLOATS 55518
#define SM_BYTES  (SM_FLOATS * 4)

__device__ float g_h[2][Bk][Dk];
__device__ float g_x[Bk][Dk];
__device__ float g_last_t[Bk];
__device__ int   g_last_m[Bk];
__device__ int   g_cand[Bk][Lk];
__device__ float g_nrec[Bk][Rk];
__device__ unsigned g_cnt[4][32];

// JAX threefry2x32 (exact)
__device__ __forceinline__ void tf2x32(uint32_t k0, uint32_t k1,
                                       uint32_t x0, uint32_t x1,
                                       uint32_t& o0, uint32_t& o1) {
  uint32_t ks2 = k0 ^ k1 ^ 0x1BD11BDAu;
  x0 += k0; x1 += k1;
#define RR(d) { x0 += x1; x1 = (x1 << d) | (x1 >> (32 - d)); x1 ^= x0; }
  RR(13) RR(15) RR(26) RR(6)  x0 += k1;  x1 += ks2 + 1u;
  RR(17) RR(29) RR(16) RR(24) x0 += ks2; x1 += k0 + 2u;
  RR(13) RR(15) RR(26) RR(6)  x0 += k0;  x1 += k1 + 3u;
  RR(17) RR(29) RR(16) RR(24) x0 += k1;  x1 += ks2 + 4u;
  RR(13) RR(15) RR(26) RR(6)  x0 += ks2; x1 += k0 + 5u;
#undef RR
  o0 = x0; o1 = x1;
}

// JAX uniform->gumbel bit recipe (exact)
__device__ __forceinline__ float gumbel_val(float pr, uint32_t k0, uint32_t k1,
                                            uint32_t i) {
  float logit = (pr > 0.0f) ? logf(fmaxf(pr, 1e-38f)) : -1e30f;
  uint32_t o0, o1;
  tf2x32(k0, k1, 0u, i, o0, o1);
  uint32_t bits = o0 ^ o1;
  float u0 = __fadd_rn(__uint_as_float((bits >> 9) | 0x3f800000u), -1.0f);
  float u = fmaxf(TINYF, __fadd_rn(u0, TINYF));
  float gq = -logf(-logf(u));
  return __fadd_rn(logit, gq);
}

__device__ __forceinline__ unsigned long long dup2(float v) {
  unsigned long long r;
  asm("mov.b64 %0, {%1, %1};" : "=l"(r) : "f"(v));
  return r;
}
__device__ __forceinline__ void ffma2(unsigned long long& acc,
                                      unsigned long long a,
                                      unsigned long long b) {
  asm("fma.rn.f32x2 %0, %1, %2, %3;" : "=l"(acc) : "l"(a), "l"(b), "l"(acc));
}
__device__ __forceinline__ unsigned long long add2(unsigned long long a,
                                                   unsigned long long b) {
  unsigned long long r;
  asm("add.rn.f32x2 %0, %1, %2;" : "=l"(r) : "l"(a), "l"(b));
  return r;
}
__device__ __forceinline__ void cpa16(uint32_t s, const void* g) {
  asm volatile("cp.async.cg.shared.global [%0], [%1], 16;"
               :: "r"(s), "l"(g) : "memory");
}
__device__ __forceinline__ void cpa_commit() {
  asm volatile("cp.async.commit_group;" ::: "memory");
}
template <int N>
__device__ __forceinline__ void cpa_wait_group() {
  asm volatile("cp.async.wait_group %0;" :: "n"(N) : "memory");
}
__device__ __forceinline__ void hbar(int id) {
  asm volatile("bar.sync %0, 256;" :: "r"(id) : "memory");
}

__global__ void reset_kernel() {
  if (threadIdx.x < 128) ((unsigned*)g_cnt)[threadIdx.x] = 0u;
}

// R8-proven barrier: release-red arrive + volatile poll on counter
__device__ __forceinline__ void gbar(int bc, unsigned& epoch) {
  __syncthreads();
  if (threadIdx.x == 0) {
    epoch += 32u;
    asm volatile("red.release.gpu.global.add.u32 [%0], %1;"
                 :: "l"(&g_cnt[bc][0]), "r"(1u) : "memory");
    while (*((volatile unsigned*)&g_cnt[bc][0]) < epoch) { }
  }
  __syncthreads();
}

__global__ void __launch_bounds__(512, 1)
rnn_persistent(const int* __restrict__ marker,
               const float* __restrict__ timed,
               const float* __restrict__ maskd,
               const float* __restrict__ emb,
               const int* __restrict__ nlist,
               const float* __restrict__ nprob,
               const float* __restrict__ W_te,
               const float* __restrict__ b_te,
               const float* __restrict__ W_el,
               const float* __restrict__ b_el,
               const float* __restrict__ W_ih,
               const float* __restrict__ b_ih,
               const float* __restrict__ W_hh,
               const float* __restrict__ b_hh,
               const float* __restrict__ W_time,
               const float* __restrict__ b_time,
               const float* __restrict__ W_mk,
               const float* __restrict__ b_mk,
               float* __restrict__ out) {
  extern __shared__ __align__(16) float SM[];
  const int BID = blockIdx.x;
  if (BID >= 128) return;
  const int tid = threadIdx.x;
  const int bc = BID >> 5;           // group (32 batch rows)
  const int dc = BID & 31;           // d tile (16 cols)
  const int myb = BID;
  unsigned epoch = 0;

  float* sP = SM + OFF_SP;

  // ---------------- one-time init ----------------
  for (int i = tid; i < Ek * 8; i += 512) {
    int e = i >> 3, dp8 = i & 7;
    ((float2*)(SM + OFF_WA))[e * 8 + dp8] =
        *(const float2*)&W_el[e * Dk + dc * 16 + dp8 * 2];
  }
  for (int i = tid; i < Dk * 8; i += 512) {
    int e = i >> 3, dp8 = i & 7;
    ((float2*)(SM + OFF_WBI))[dp8 * 514 + e] =
        *(const float2*)&W_ih[e * Dk + dc * 16 + dp8 * 2];
    ((float2*)(SM + OFF_WBH))[dp8 * 514 + e] =
        *(const float2*)&W_hh[e * Dk + dc * 16 + dp8 * 2];
  }
  for (int i = tid; i < Ek + Dk; i += 512) SM[OFF_WMK + i] = W_mk[i];
  if (tid < Dk) {
    SM[OFF_WTM + tid] = W_time[tid];
    SM[OFF_BEL + tid] = b_el[tid];
    SM[OFF_BIH + tid] = b_ih[tid];
    SM[OFF_BHH + tid] = b_hh[tid];
  }
  if (tid < Ek) { SM[OFF_WTE + tid] = W_te[tid]; SM[OFF_BTE + tid] = b_te[tid]; }
  if (tid == 0) {
    SM[OFF_BT] = b_time[0]; SM[OFF_BT + 1] = b_mk[0];
    SM[OFF_BT + 2] = timed[myb * Sk];
  }
  for (int l = tid; l < Lk; l += 512) {
    sP[l] = (l == 0) ? 1.0f : 0.0f;
    g_cand[myb][l] = (l == 0) ? marker[myb * Sk] : 0;
  }
  for (int r = tid; r < Rk; r += 512) g_nrec[myb][r] = 1.0f;
  for (int d = tid; d < Dk; d += 512) __stcg(&g_h[0][myb][d], 0.0f);
  int chosen = 0;
  if (tid == 0) {
    __stcg(&g_last_t[myb], timed[myb * Sk]);
    __stcg(&g_last_m[myb], marker[myb * Sk]);
    out[0 * 16384 + myb * Sk] = (float)marker[myb * Sk];
    out[1 * 16384 + myb * Sk] = timed[myb * Sk];
    out[2 * 16384 + myb * Sk] = maskd[myb * Sk];
    out[3 * 16384 + myb * Sk] = 1.0f;
    out[4 * 16384 + myb * Sk] = 1.0f;
  }
  gbar(bc, epoch);

  const int half = tid >> 8;          // 0: x-part, 1: h-part
  const int htid = tid & 255;
  const int dp = htid & 7;            // phase-A mapping
  const int blw = htid >> 3;
  const int d0 = dc * 16 + dp * 2;
  const int bg = bc * 32 + blw;
  // phase-B FMA mapping (4 rows per thread, htid<64)
  const int fdp = htid & 7;
  const int frg = (htid >> 3) & 7;    // 0..7
  const int d0f = dc * 16 + fdp * 2;
  const int warp = tid >> 5, lane = tid & 31;
  float* red  = SM + OFF_CS;            // [16]
  float* redv = SM + OFF_CS + 16;       // [16]
  int*   ri   = (int*)(SM + OFF_CS + 32);
  int*   s_neigh = (int*)(SM + OFF_CS + 48);
  float* s_score = SM + OFF_CS + 64;
  float* redp = SM + OFF_CS + 80;       // [12]
  int*   ripre = (int*)(SM + OFF_CS + 92);  // [12]
  unsigned long long* sCMB = (unsigned long long*)(SM + OFF_CMB);
  const uint32_t stA = (uint32_t)__cvta_generic_to_shared(SM + OFF_BUFA);
  const uint32_t stB = (uint32_t)__cvta_generic_to_shared(SM + OFF_BUFB);
  const uint32_t stC = (uint32_t)__cvta_generic_to_shared(SM + OFF_BUFC);
  const uint32_t se_base = (uint32_t)__cvta_generic_to_shared(SM + OFF_SE);

#define STAGE_H(gptr, ebase, dst)                                         \
  {                                                                       \
    _Pragma("unroll")                                                     \
    for (int j = 0; j < 8; j++) {                                         \
      int id = htid + j * 256;                                            \
      int rr = id >> 6, seg = id & 63;                                    \
      cpa16((dst) + (uint32_t)(rr * 260 + seg * 4) * 4,                   \
            (gptr) + (size_t)(bc * 32 + rr) * Dk + (ebase) + seg * 4);    \
    }                                                                     \
    cpa_commit();                                                         \
  }
  // 4-row register-blocked chunk: rows frg, frg+8, frg+16, frg+24.
  // Per-row accumulation pattern identical to R13's CHUNK2.
#define CHUNK4(wbase, ehalf, buf)                                         \
  {                                                                       \
    const float4* p0 = (const float4*)(SM + (buf) + frg * 260);           \
    const float4* p1 = (const float4*)(SM + (buf) + (frg + 8) * 260);     \
    const float4* p2 = (const float4*)(SM + (buf) + (frg + 16) * 260);    \
    const float4* p3 = (const float4*)(SM + (buf) + (frg + 24) * 260);    \
    const ulonglong2* pw =                                                \
        (const ulonglong2*)(SM + (wbase)) + fdp * 257 + (ehalf) * 128;    \
    _Pragma("unroll 4")                                                   \
    for (int e4 = 0; e4 < 64; e4++) {                                     \
      ulonglong2 wA = pw[2 * e4], wB = pw[2 * e4 + 1];                    \
      float4 q0 = p0[e4]; float4 q1 = p1[e4];                             \
      float4 q2 = p2[e4]; float4 q3 = p3[e4];                             \
      ffma2(A0, dup2(q0.x), wA.x); ffma2(A1, dup2(q0.y), wA.y);           \
      ffma2(A0, dup2(q0.z), wB.x); ffma2(A1, dup2(q0.w), wB.y);           \
      ffma2(B0, dup2(q1.x), wA.x); ffma2(B1, dup2(q1.y), wA.y);           \
      ffma2(B0, dup2(q1.z), wB.x); ffma2(B1, dup2(q1.w), wB.y);           \
      ffma2(C0, dup2(q2.x), wA.x); ffma2(C1, dup2(q2.y), wA.y);           \
      ffma2(C0, dup2(q2.z), wB.x); ffma2(C1, dup2(q2.w), wB.y);           \
      ffma2(D0, dup2(q3.x), wA.x); ffma2(D1, dup2(q3.y), wA.y);           \
      ffma2(D0, dup2(q3.z), wB.x); ffma2(D1, dup2(q3.w), wB.y);           \
    }                                                                     \
  }
  // prescan over untouched l in [0, 1+15t) \ {chosen}; 384 threads, 12 slots
#define PRESCAN()                                                         \
  {                                                                       \
    int ptid = (htid - 64) + half * 192;                                  \
    int base_p = 1 + t * (Kk - 1);                                        \
    uint32_t pk0, pk1;                                                    \
    tf2x32(0u, 42u, 0u, (uint32_t)t, pk0, pk1);                           \
    float bvp = -3.4e38f; int bip = 0x7fffffff;                           \
    for (int l = ptid; l < base_p; l += 384) {                            \
      if (l == chosen) continue;                                          \
      float v = gumbel_val(sP[l], pk0, pk1, (uint32_t)(myb * Lk + l));    \
      if (v > bvp) { bvp = v; bip = l; }                                  \
    }                                                                     \
    for (int o = 16; o; o >>= 1) {                                        \
      float ov = __shfl_down_sync(0xffffffffu, bvp, o);                   \
      int   oi = __shfl_down_sync(0xffffffffu, bip, o);                   \
      if (ov > bvp || (ov == bvp && oi < bip)) { bvp = ov; bip = oi; }    \
    }                                                                     \
    if (lane == 0) {                                                      \
      int slot = (warp < 8) ? (warp - 2) : (warp - 4);                    \
      redp[slot] = bvp; ripre[slot] = bip;                                \
    }                                                                     \
  }

  for (int t = 0; t < Tk; t++) {
    const float* hin = &g_h[t & 1][0][0];
    // ============ Phase A: x = leaky(vec @ W_el + b_el) ============
    {
      if (tid < 32) {
        SM[OFF_SLT + tid] = __ldcg(&g_last_t[bc * 32 + tid]);
        ((int*)(SM + OFF_SLM))[tid] = __ldcg(&g_last_m[bc * 32 + tid]);
      }
      __syncthreads();
#pragma unroll
      for (int j = 0; j < 4; j++) {
        int id = tid + j * 512;
        int bl = id >> 6, seg = id & 63;
        cpa16(stA + (uint32_t)(bl * 260 + seg * 4) * 4,
              emb + (size_t)((int*)(SM + OFF_SLM))[bl] * Ek + seg * 4);
      }
      cpa_commit();
      if (half == 1) {
        STAGE_H(hin, 0, stB)
        STAGE_H(hin, 256, stC)
        cpa_wait_group<2>();   // emb done
      } else {
        cpa_wait_group<0>();   // emb done
      }
      __syncthreads();
      {
        int e = tid & 255;
        float wte = SM[OFF_WTE + e], bte = SM[OFF_BTE + e];
        float* sV = SM + OFF_BUFA;
#pragma unroll 4
        for (int bl = half * 16; bl < half * 16 + 16; bl++) {
          float te = __fadd_rn(__fmul_rn(SM[OFF_SLT + bl], wte), bte);
          sV[bl * 260 + e] = __fadd_rn(sV[bl * 260 + e], __fmul_rn(0.1f, te));
        }
      }
      __syncthreads();
      // dot: each half its e-range
      {
        const float* pv = SM + OFF_BUFA + blw * 260 + half * 128;
        const unsigned long long* wa =
            (const unsigned long long*)(SM + OFF_WA) + half * 128 * 8;
        unsigned long long c0 = 0ull, c1 = 0ull;
#pragma unroll 8
        for (int e = 0; e < 128; e += 2) {
          ffma2(c0, dup2(pv[e]), wa[e * 8 + dp]);
          ffma2(c1, dup2(pv[e + 1]), wa[(e + 1) * 8 + dp]);
        }
        unsigned long long aH = add2(c0, c1);
        if (half == 1) sCMB[htid] = aH;
        __syncthreads();
        if (half == 0) {
          unsigned long long accT = add2(aH, sCMB[htid]);
          float v0, v1;
          asm("mov.b64 {%0, %1}, %2;" : "=f"(v0), "=f"(v1) : "l"(accT));
          v0 = __fadd_rn(v0, SM[OFF_BEL + d0]);
          v1 = __fadd_rn(v1, SM[OFF_BEL + d0 + 1]);
          float2 r;
          r.x = (v0 >= 0.0f) ? v0 : __fmul_rn(0.01f, v0);
          r.y = (v1 >= 0.0f) ? v1 : __fmul_rn(0.01f, v1);
          __stcg((float2*)&g_x[bg][d0], r);
        }
      }
      int lm_my = ((int*)(SM + OFF_SLM))[dc];
      if (tid < Kk) {
        s_neigh[tid] = nlist[lm_my * Kk + tid];
        g_nrec[myb][1 + t * Kk + tid] = nprob[lm_my * Kk + tid];
      }
      __syncthreads();
#pragma unroll
      for (int j = 0; j < 2; j++) {
        int id = tid + j * 512;
        int k = id >> 6, seg = id & 63;
        cpa16(se_base + (uint32_t)(k * 256 + seg * 4) * 4,
              emb + (size_t)s_neigh[k] * Ek + seg * 4);
      }
      cpa_commit();
    }
    gbar(bc, epoch);

    // ==== Phase B: blocked FMA (64 thr/half) + prescan (192 thr/half) ====
    {
      unsigned long long A0 = 0ull, A1 = 0ull, B0 = 0ull, B1 = 0ull;
      unsigned long long C0 = 0ull, C1 = 0ull, D0 = 0ull, D1 = 0ull;
      if (half == 0) {
        STAGE_H(&g_x[0][0], 0, stA)     // x0 -> A (all 256)
        cpa_wait_group<0>();
        hbar(1);                        // x0 visible
        if (htid < 64) { CHUNK4(OFF_WBI, 0, OFF_BUFA) }
        else           { PRESCAN() }
        hbar(1);                        // x0 consumed
        STAGE_H(&g_x[0][0], 256, stA)   // x1 -> A
        cpa_wait_group<0>();
        hbar(1);                        // x1 visible
        if (htid < 64) { CHUNK4(OFF_WBI, 1, OFF_BUFA) }
      } else {
        cpa_wait_group<1>();            // h0,h1 done (SE may pend)
        hbar(2);                        // h visible
        if (htid < 64) {
          CHUNK4(OFF_WBH, 0, OFF_BUFB)
          CHUNK4(OFF_WBH, 1, OFF_BUFC)
          sCMB[frg * 8 + fdp]          = add2(A0, A1);
          sCMB[(frg + 8) * 8 + fdp]    = add2(B0, B1);
          sCMB[(frg + 16) * 8 + fdp]   = add2(C0, C1);
          sCMB[(frg + 24) * 8 + fdp]   = add2(D0, D1);
        } else {
          PRESCAN()
        }
      }
      __syncthreads();
      if (tid < 64) {   // half0 FMA threads: combine + write 4 rows
        float bi0 = SM[OFF_BIH + d0f], bi1 = SM[OFF_BIH + d0f + 1];
        float bh0 = SM[OFF_BHH + d0f], bh1 = SM[OFF_BHH + d0f + 1];
        unsigned long long axR[4] = {add2(A0, A1), add2(B0, B1),
                                     add2(C0, C1), add2(D0, D1)};
#pragma unroll
        for (int rr = 0; rr < 4; rr++) {
          int row = frg + rr * 8;
          unsigned long long ahR = sCMB[row * 8 + fdp];
          float xv0, xv1, hv0, hv1;
          asm("mov.b64 {%0, %1}, %2;" : "=f"(xv0), "=f"(xv1) : "l"(axR[rr]));
          asm("mov.b64 {%0, %1}, %2;" : "=f"(hv0), "=f"(hv1) : "l"(ahR));
          float2 r;
          r.x = tanhf(__fadd_rn(__fadd_rn(__fadd_rn(xv0, bi0), hv0), bh0));
          r.y = tanhf(__fadd_rn(__fadd_rn(__fadd_rn(xv1, bi1), hv1), bh1));
          __stcg((float2*)&g_h[(t + 1) & 1][bc * 32 + row][d0f], r);
        }
      }
    }
    gbar(bc, epoch);

    // ============ Phase C: lightweight sampling (fresh-16 + merge) ========
    {
      float* hb = SM + OFF_BUFA;            // [512]
      float* sE = SM + OFF_SE;

      cpa_wait_group<0>();                  // SE landed
      hb[tid] = __ldcg(&g_h[(t + 1) & 1][myb][tid]);
      __syncthreads();

      // dt partial + warp reduce
      {
        float a = __fmul_rn(hb[tid], SM[OFF_WTM + tid]);
        for (int o = 16; o; o >>= 1)
          a = __fadd_rn(a, __shfl_down_sync(0xffffffffu, a, o));
        if (lane == 0) red[warp] = a;
      }

      // neighbor scores: warp k
      {
        const float* ev = sE + warp * 256;
        float acc0 = 0.0f, acc1 = 0.0f;
#pragma unroll
        for (int i = lane; i < Ek + Dk; i += 64) {
          float v0 = (i < Ek) ? ev[i] : hb[i - Ek];
          int i2 = i + 32;
          float v1 = (i2 < Ek) ? ev[i2] : hb[i2 - Ek];
          acc0 = fmaf(v0, SM[OFF_WMK + i], acc0);
          acc1 = fmaf(v1, SM[OFF_WMK + i2], acc1);
        }
        float acc = __fadd_rn(acc0, acc1);
        for (int o = 16; o; o >>= 1) acc += __shfl_down_sync(0xffffffffu, acc, o);
        if (lane == 0) s_score[warp] = __fadd_rn(acc, SM[OFF_BT + 1]);
      }
      __syncthreads();

      float newt = 0.0f;
      if (tid == 0) {
        float s = red[0];
        for (int w = 1; w < 16; w++) s = __fadd_rn(s, red[w]);
        float xx = __fadd_rn(s, SM[OFF_BT]);
        float sp = __fadd_rn(fmaxf(xx, 0.0f), log1pf(expf(-fabsf(xx))));
        newt = __fadd_rn(SM[OFF_BT + 2], sp);
      }

      // softmax + prob/cand updates + fresh-16 gumbel on warp 0
      if (warp == 0) {
        float sc = (lane < Kk) ? s_score[lane] : -3.4e38f;
        float mx = sc;
        for (int o = 8; o; o >>= 1)
          mx = fmaxf(mx, __shfl_xor_sync(0xffffffffu, mx, o));
        float ek = (lane < Kk) ? expf(__fadd_rn(sc, -mx)) : 0.0f;
        float ssum = 0.0f;
#pragma unroll
        for (int k = 0; k < Kk; k++)
          ssum = __fadd_rn(ssum, __shfl_sync(0xffffffffu, ek, k));
        float cp = sP[chosen];
        __syncwarp();
        float fv = -3.4e38f; int fi = 0x7fffffff;
        int base = 1 + t * (Kk - 1);
        if (lane < Kk) {
          float att = __fmul_rn(cp, __fdiv_rn(ek, ssum));
          int lf;
          if (lane == 0) {
            sP[chosen] = att;
            lf = chosen;
          } else {
            sP[base + lane - 1] = att;
            g_cand[myb][base + lane - 1] = s_neigh[lane];
            lf = base + lane - 1;
          }
          uint32_t ck0, ck1;
          tf2x32(0u, 42u, 0u, (uint32_t)t, ck0, ck1);
          fv = gumbel_val(att, ck0, ck1, (uint32_t)(myb * Lk + lf));
          fi = lf;
        }
        for (int o = 16; o; o >>= 1) {
          float ov = __shfl_down_sync(0xffffffffu, fv, o);
          int   oi = __shfl_down_sync(0xffffffffu, fi, o);
          if (ov > fv || (ov == fv && oi < fi)) { fv = ov; fi = oi; }
        }
        if (lane == 0) { redv[0] = fv; ri[0] = fi; }
      }
      __syncthreads();

      // merge fresh best with 12 prescan partials
      float bestv = redv[0]; int besti = ri[0];
#pragma unroll
      for (int s = 0; s < 12; s++) {
        float pv2 = redp[s]; int pi2 = ripre[s];
        if (pv2 > bestv || (pv2 == bestv && pi2 < besti)) {
          bestv = pv2; besti = pi2;
        }
      }
      chosen = besti;
      if (tid == 0) {
        int nm = g_cand[myb][besti];
        int col = t + 1;
        out[0 * 16384 + myb * Sk + col] = (float)nm;
        out[1 * 16384 + myb * Sk + col] = newt;
        out[2 * 16384 + myb * Sk + col] = (newt < 1000.0f) ? 1.0f : 0.0f;
        out[3 * 16384 + myb * Sk + col] = g_nrec[myb][besti];
        out[4 * 16384 + myb * Sk + col] = sP[besti];
        SM[OFF_BT + 2] = newt;
        __stcg(&g_last_m[myb], nm);
        __stcg(&g_last_t[myb], newt);
      }
    }
    gbar(bc, epoch);
  }
#undef STAGE_H
#undef CHUNK4
#undef PRESCAN
}

extern "C" void kernel_launch(void* const* d_in, const int* in_sizes, int n_in,
                              void* d_out, int out_size) {
  const int*   marker = (const int*)d_in[0];
  const float* timed  = (const float*)d_in[1];
  const float* maskd  = (const float*)d_in[2];
  const float* emb    = (const float*)d_in[3];
  const int*   nlist  = (const int*)d_in[4];
  const float* nprob  = (const float*)d_in[5];
  const float* W_te   = (const float*)d_in[6];
  const float* b_te   = (const float*)d_in[7];
  const float* W_el   = (const float*)d_in[8];
  const float* b_el   = (const float*)d_in[9];
  const float* W_ih   = (const float*)d_in[10];
  const float* b_ih   = (const float*)d_in[11];
  const float* W_hh   = (const float*)d_in[12];
  const float* b_hh   = (const float*)d_in[13];
  const float* W_time = (const float*)d_in[14];
  const float* b_time = (const float*)d_in[15];
  const float* W_mk   = (const float*)d_in[16];
  const float* b_mk   = (const float*)d_in[17];
  float* out = (float*)d_out;

  cudaFuncSetAttribute(rnn_persistent,
                       cudaFuncAttributeMaxDynamicSharedMemorySize, SM_BYTES);
  reset_kernel<<<1, 128>>>();
  rnn_persistent<<<148, 512, SM_BYTES>>>(marker, timed, maskd, emb, nlist, nprob,
                                         W_te, b_te, W_el, b_el, W_ih, b_ih,
                                         W_hh, b_hh, W_time, b_time, W_mk, b_mk,
                                         out);
}

// round 15
// speedup vs baseline: 1.0717x; 1.0717x over previous
#include <cuda_runtime.h>
#include <cstdint>

#define Bk 128
#define Sk 128
#define Ek 256
#define Dk 512
#define Kk 16
#define Lk 1906
#define Rk 2033
#define Tk 127
#define TINYF 1.17549435e-38f

// smem layout (float offsets)
#define OFF_BUFA  0        // 32x260
#define OFF_BUFB  8320     // 32x260
#define OFF_BUFC  16640    // 32x260
#define OFF_WA    24960    // 256e x 8dp float2 = 4096
#define OFF_WBI   29056    // 8dp x 514 float2 = 8224
#define OFF_WBH   37280
#define OFF_SE    45504    // 16x256 = 4096
#define OFF_WMK   49600    // 768
#define OFF_WTM   50368    // 512
#define OFF_WTE   50880    // 256
#define OFF_BTE   51136    // 256
#define OFF_BEL   51392    // 512
#define OFF_BIH   51904    // 512
#define OFF_BHH   52416    // 512
#define OFF_BT    52928    // 4: b_time, b_mk, last_t_my
#define OFF_SLT   52932    // 32
#define OFF_SLM   52964    // 32
#define OFF_CS    52996    // red16 redv16 ri16 neigh16 score16 redp8 ripre8 red2_16
#define OFF_CMB   53116    // 256 ULL (8B aligned: even)
#define OFF_SP    53628    // prob[1906]
#define OFF_PQ    55534    // P[16], Q[16]
#define SM_FLOATS 55566
#define SM_BYTES  (SM_FLOATS * 4)

__device__ float g_h[2][Bk][Dk];
__device__ float g_x[Bk][Dk];
__device__ float g_last_t[Bk];
__device__ int   g_last_m[Bk];
__device__ int   g_cand[Bk][Lk];
__device__ float g_nrec[Bk][Rk];
__device__ unsigned g_cnt[4][32];

// JAX threefry2x32 (exact)
__device__ __forceinline__ void tf2x32(uint32_t k0, uint32_t k1,
                                       uint32_t x0, uint32_t x1,
                                       uint32_t& o0, uint32_t& o1) {
  uint32_t ks2 = k0 ^ k1 ^ 0x1BD11BDAu;
  x0 += k0; x1 += k1;
#define RR(d) { x0 += x1; x1 = (x1 << d) | (x1 >> (32 - d)); x1 ^= x0; }
  RR(13) RR(15) RR(26) RR(6)  x0 += k1;  x1 += ks2 + 1u;
  RR(17) RR(29) RR(16) RR(24) x0 += ks2; x1 += k0 + 2u;
  RR(13) RR(15) RR(26) RR(6)  x0 += k0;  x1 += k1 + 3u;
  RR(17) RR(29) RR(16) RR(24) x0 += k1;  x1 += ks2 + 4u;
  RR(13) RR(15) RR(26) RR(6)  x0 += ks2; x1 += k0 + 5u;
#undef RR
  o0 = x0; o1 = x1;
}

// JAX uniform->gumbel bit recipe (exact)
__device__ __forceinline__ float gumbel_val(float pr, uint32_t k0, uint32_t k1,
                                            uint32_t i) {
  float logit = (pr > 0.0f) ? logf(fmaxf(pr, 1e-38f)) : -1e30f;
  uint32_t o0, o1;
  tf2x32(k0, k1, 0u, i, o0, o1);
  uint32_t bits = o0 ^ o1;
  float u0 = __fadd_rn(__uint_as_float((bits >> 9) | 0x3f800000u), -1.0f);
  float u = fmaxf(TINYF, __fadd_rn(u0, TINYF));
  float gq = -logf(-logf(u));
  return __fadd_rn(logit, gq);
}

__device__ __forceinline__ unsigned long long dup2(float v) {
  unsigned long long r;
  asm("mov.b64 %0, {%1, %1};" : "=l"(r) : "f"(v));
  return r;
}
__device__ __forceinline__ void ffma2(unsigned long long& acc,
                                      unsigned long long a,
                                      unsigned long long b) {
  asm("fma.rn.f32x2 %0, %1, %2, %3;" : "=l"(acc) : "l"(a), "l"(b), "l"(acc));
}
__device__ __forceinline__ unsigned long long add2(unsigned long long a,
                                                   unsigned long long b) {
  unsigned long long r;
  asm("add.rn.f32x2 %0, %1, %2;" : "=l"(r) : "l"(a), "l"(b));
  return r;
}
__device__ __forceinline__ void cpa16(uint32_t s, const void* g) {
  asm volatile("cp.async.cg.shared.global [%0], [%1], 16;"
               :: "r"(s), "l"(g) : "memory");
}
__device__ __forceinline__ void cpa_commit() {
  asm volatile("cp.async.commit_group;" ::: "memory");
}
template <int N>
__device__ __forceinline__ void cpa_wait_group() {
  asm volatile("cp.async.wait_group %0;" :: "n"(N) : "memory");
}
__device__ __forceinline__ void hbar(int id) {
  asm volatile("bar.sync %0, 256;" :: "r"(id) : "memory");
}

__global__ void reset_kernel() {
  if (threadIdx.x < 128) ((unsigned*)g_cnt)[threadIdx.x] = 0u;
}

// R8-proven barrier: release-red arrive + volatile poll on counter
__device__ __forceinline__ void gbar(int bc, unsigned& epoch) {
  __syncthreads();
  if (threadIdx.x == 0) {
    epoch += 32u;
    asm volatile("red.release.gpu.global.add.u32 [%0], %1;"
                 :: "l"(&g_cnt[bc][0]), "r"(1u) : "memory");
    while (*((volatile unsigned*)&g_cnt[bc][0]) < epoch) { }
  }
  __syncthreads();
}

__global__ void __launch_bounds__(512, 1)
rnn_persistent(const int* __restrict__ marker,
               const float* __restrict__ timed,
               const float* __restrict__ maskd,
               const float* __restrict__ emb,
               const int* __restrict__ nlist,
               const float* __restrict__ nprob,
               const float* __restrict__ W_te,
               const float* __restrict__ b_te,
               const float* __restrict__ W_el,
               const float* __restrict__ b_el,
               const float* __restrict__ W_ih,
               const float* __restrict__ b_ih,
               const float* __restrict__ W_hh,
               const float* __restrict__ b_hh,
               const float* __restrict__ W_time,
               const float* __restrict__ b_time,
               const float* __restrict__ W_mk,
               const float* __restrict__ b_mk,
               float* __restrict__ out) {
  extern __shared__ __align__(16) float SM[];
  const int BID = blockIdx.x;
  if (BID >= 128) return;
  const int tid = threadIdx.x;
  const int bc = BID >> 5;           // group (32 batch rows)
  const int dc = BID & 31;           // d tile (16 cols)
  const int myb = BID;
  unsigned epoch = 0;

  float* sP = SM + OFF_SP;
  const int warp = tid >> 5, lane = tid & 31;

  // ---------------- one-time init ----------------
  for (int i = tid; i < Ek * 8; i += 512) {
    int e = i >> 3, dp8 = i & 7;
    ((float2*)(SM + OFF_WA))[e * 8 + dp8] =
        *(const float2*)&W_el[e * Dk + dc * 16 + dp8 * 2];
  }
  for (int i = tid; i < Dk * 8; i += 512) {
    int e = i >> 3, dp8 = i & 7;
    ((float2*)(SM + OFF_WBI))[dp8 * 514 + e] =
        *(const float2*)&W_ih[e * Dk + dc * 16 + dp8 * 2];
    ((float2*)(SM + OFF_WBH))[dp8 * 514 + e] =
        *(const float2*)&W_hh[e * Dk + dc * 16 + dp8 * 2];
  }
  for (int i = tid; i < Ek + Dk; i += 512) SM[OFF_WMK + i] = W_mk[i];
  if (tid < Dk) {
    SM[OFF_WTM + tid] = W_time[tid];
    SM[OFF_BEL + tid] = b_el[tid];
    SM[OFF_BIH + tid] = b_ih[tid];
    SM[OFF_BHH + tid] = b_hh[tid];
  }
  if (tid < Ek) { SM[OFF_WTE + tid] = W_te[tid]; SM[OFF_BTE + tid] = b_te[tid]; }
  if (tid == 0) {
    SM[OFF_BT] = b_time[0]; SM[OFF_BT + 1] = b_mk[0];
    SM[OFF_BT + 2] = timed[myb * Sk];
  }
  for (int l = tid; l < Lk; l += 512) {
    sP[l] = (l == 0) ? 1.0f : 0.0f;
    g_cand[myb][l] = (l == 0) ? marker[myb * Sk] : 0;
  }
  for (int r = tid; r < Rk; r += 512) g_nrec[myb][r] = 1.0f;
  for (int d = tid; d < Dk; d += 512) __stcg(&g_h[0][myb][d], 0.0f);
  int chosen = 0;
  if (tid == 0) {
    __stcg(&g_last_t[myb], timed[myb * Sk]);
    __stcg(&g_last_m[myb], marker[myb * Sk]);
    out[0 * 16384 + myb * Sk] = (float)marker[myb * Sk];
    out[1 * 16384 + myb * Sk] = timed[myb * Sk];
    out[2 * 16384 + myb * Sk] = maskd[myb * Sk];
    out[3 * 16384 + myb * Sk] = 1.0f;
    out[4 * 16384 + myb * Sk] = 1.0f;
  }
  __syncthreads();
  // P[d] = sum_e wte[e]*W_el[e][d], Q[d] = sum_e bte[e]*W_el[e][d]
  {
    int w = warp;                         // one local d per warp (16 warps)
    float sp_ = 0.0f, sq_ = 0.0f;
    for (int e = lane; e < Ek; e += 32) {
      float2 wv = ((float2*)(SM + OFF_WA))[e * 8 + (w >> 1)];
      float wd = (w & 1) ? wv.y : wv.x;
      sp_ = fmaf(SM[OFF_WTE + e], wd, sp_);
      sq_ = fmaf(SM[OFF_BTE + e], wd, sq_);
    }
    for (int o = 16; o; o >>= 1) {
      sp_ += __shfl_down_sync(0xffffffffu, sp_, o);
      sq_ += __shfl_down_sync(0xffffffffu, sq_, o);
    }
    if (lane == 0) { SM[OFF_PQ + w] = sp_; SM[OFF_PQ + 16 + w] = sq_; }
  }
  gbar(bc, epoch);

  const int half = tid >> 8;          // 0: x-part, 1: h-part
  const int htid = tid & 255;
  const int dp = htid & 7;            // phase-A mapping
  const int blw = htid >> 3;
  const int d0 = dc * 16 + dp * 2;
  const int bg = bc * 32 + blw;
  // phase-B FMA mapping (2 rows per thread, htid<128)
  const int fdp = htid & 7;
  const int frg = (htid >> 3) & 15;
  const int d0f = dc * 16 + fdp * 2;
  float* red  = SM + OFF_CS;            // [16]
  float* redv = SM + OFF_CS + 16;       // [16]
  int*   ri   = (int*)(SM + OFF_CS + 32);
  int*   s_neigh = (int*)(SM + OFF_CS + 48);
  float* s_score = SM + OFF_CS + 64;
  float* redp = SM + OFF_CS + 80;       // [8]
  int*   ripre = (int*)(SM + OFF_CS + 92);  // [8] (88..95 shifted: use 92)
  float* red2 = SM + OFF_CS + 104;      // [16] hmk partials
  unsigned long long* sCMB = (unsigned long long*)(SM + OFF_CMB);
  const uint32_t stA = (uint32_t)__cvta_generic_to_shared(SM + OFF_BUFA);
  const uint32_t stB = (uint32_t)__cvta_generic_to_shared(SM + OFF_BUFB);
  const uint32_t stC = (uint32_t)__cvta_generic_to_shared(SM + OFF_BUFC);
  const uint32_t se_base = (uint32_t)__cvta_generic_to_shared(SM + OFF_SE);

#define STAGE_H(gptr, ebase, dst)                                         \
  {                                                                       \
    _Pragma("unroll")                                                     \
    for (int j = 0; j < 8; j++) {                                         \
      int id = htid + j * 256;                                            \
      int rr = id >> 6, seg = id & 63;                                    \
      cpa16((dst) + (uint32_t)(rr * 260 + seg * 4) * 4,                   \
            (gptr) + (size_t)(bc * 32 + rr) * Dk + (ebase) + seg * 4);    \
    }                                                                     \
    cpa_commit();                                                         \
  }
  // 2-row register-blocked chunk (R13-proven)
#define CHUNK2(wbase, ehalf, buf)                                         \
  {                                                                       \
    const float4* p0 = (const float4*)(SM + (buf) + frg * 260);           \
    const float4* p1 = (const float4*)(SM + (buf) + (frg + 16) * 260);    \
    const ulonglong2* pw =                                                \
        (const ulonglong2*)(SM + (wbase)) + fdp * 257 + (ehalf) * 128;    \
    _Pragma("unroll 8")                                                   \
    for (int e4 = 0; e4 < 64; e4++) {                                     \
      float4 q0 = p0[e4]; float4 q1 = p1[e4];                             \
      ulonglong2 wA = pw[2 * e4], wB = pw[2 * e4 + 1];                    \
      ffma2(a0, dup2(q0.x), wA.x); ffma2(b0, dup2(q1.x), wA.x);           \
      ffma2(a1, dup2(q0.y), wA.y); ffma2(b1, dup2(q1.y), wA.y);           \
      ffma2(a0, dup2(q0.z), wB.x); ffma2(b0, dup2(q1.z), wB.x);           \
      ffma2(a1, dup2(q0.w), wB.y); ffma2(b1, dup2(q1.w), wB.y);           \
    }                                                                     \
  }
  // prescan over untouched l in [0, 1+15t) \ {chosen}; 256 threads, 8 slots
#define PRESCAN()                                                         \
  {                                                                       \
    int ptid = (tid < 256) ? (tid - 128) : (tid - 256);                   \
    int base_p = 1 + t * (Kk - 1);                                        \
    uint32_t pk0, pk1;                                                    \
    tf2x32(0u, 42u, 0u, (uint32_t)t, pk0, pk1);                           \
    float bvp = -3.4e38f; int bip = 0x7fffffff;                           \
    for (int l = ptid; l < base_p; l += 256) {                            \
      if (l == chosen) continue;                                          \
      float v = gumbel_val(sP[l], pk0, pk1, (uint32_t)(myb * Lk + l));    \
      if (v > bvp) { bvp = v; bip = l; }                                  \
    }                                                                     \
    for (int o = 16; o; o >>= 1) {                                        \
      float ov = __shfl_down_sync(0xffffffffu, bvp, o);                   \
      int   oi = __shfl_down_sync(0xffffffffu, bip, o);                   \
      if (ov > bvp || (ov == bvp && oi < bip)) { bvp = ov; bip = oi; }    \
    }                                                                     \
    if (lane == 0) {                                                      \
      int slot = (warp < 8) ? (warp - 4) : (warp - 8);                    \
      redp[slot] = bvp; ripre[slot] = bip;                                \
    }                                                                     \
  }

  for (int t = 0; t < Tk; t++) {
    const float* hin = &g_h[t & 1][0][0];
    // ============ Phase A: x = leaky(emb_dot + 0.1*(lt*P+Q) + b_el) ========
    {
      if (tid < 32) {
        SM[OFF_SLT + tid] = __ldcg(&g_last_t[bc * 32 + tid]);
        ((int*)(SM + OFF_SLM))[tid] = __ldcg(&g_last_m[bc * 32 + tid]);
      }
      __syncthreads();
#pragma unroll
      for (int j = 0; j < 4; j++) {
        int id = tid + j * 512;
        int bl = id >> 6, seg = id & 63;
        cpa16(stA + (uint32_t)(bl * 260 + seg * 4) * 4,
              emb + (size_t)((int*)(SM + OFF_SLM))[bl] * Ek + seg * 4);
      }
      cpa_commit();
      if (half == 1) {
        STAGE_H(hin, 0, stB)
        STAGE_H(hin, 256, stC)
        cpa_wait_group<2>();   // emb done
      } else {
        cpa_wait_group<0>();   // emb done
      }
      __syncthreads();
      // dot on raw emb: each half its e-range
      {
        const float* pv = SM + OFF_BUFA + blw * 260 + half * 128;
        const unsigned long long* wa =
            (const unsigned long long*)(SM + OFF_WA) + half * 128 * 8;
        unsigned long long c0 = 0ull, c1 = 0ull;
#pragma unroll 8
        for (int e = 0; e < 128; e += 2) {
          ffma2(c0, dup2(pv[e]), wa[e * 8 + dp]);
          ffma2(c1, dup2(pv[e + 1]), wa[(e + 1) * 8 + dp]);
        }
        unsigned long long aH = add2(c0, c1);
        if (half == 1) sCMB[htid] = aH;
        __syncthreads();
        if (half == 0) {
          unsigned long long accT = add2(aH, sCMB[htid]);
          float v0, v1;
          asm("mov.b64 {%0, %1}, %2;" : "=f"(v0), "=f"(v1) : "l"(accT));
          float lt = SM[OFF_SLT + blw];
          float c0f = fmaf(lt, SM[OFF_PQ + dp * 2],     SM[OFF_PQ + 16 + dp * 2]);
          float c1f = fmaf(lt, SM[OFF_PQ + dp * 2 + 1], SM[OFF_PQ + 17 + dp * 2]);
          v0 = fmaf(0.1f, c0f, v0);
          v1 = fmaf(0.1f, c1f, v1);
          v0 = __fadd_rn(v0, SM[OFF_BEL + d0]);
          v1 = __fadd_rn(v1, SM[OFF_BEL + d0 + 1]);
          float2 r;
          r.x = (v0 >= 0.0f) ? v0 : __fmul_rn(0.01f, v0);
          r.y = (v1 >= 0.0f) ? v1 : __fmul_rn(0.01f, v1);
          __stcg((float2*)&g_x[bg][d0], r);
        }
      }
      int lm_my = ((int*)(SM + OFF_SLM))[dc];
      if (tid < Kk) {
        s_neigh[tid] = nlist[lm_my * Kk + tid];
        g_nrec[myb][1 + t * Kk + tid] = nprob[lm_my * Kk + tid];
      }
      __syncthreads();
#pragma unroll
      for (int j = 0; j < 2; j++) {
        int id = tid + j * 512;
        int k = id >> 6, seg = id & 63;
        cpa16(se_base + (uint32_t)(k * 256 + seg * 4) * 4,
              emb + (size_t)s_neigh[k] * Ek + seg * 4);
      }
      cpa_commit();
    }
    gbar(bc, epoch);

    // ==== Phase B: blocked FMA (128 thr/half) + prescan (128 thr/half) ====
    {
      unsigned long long a0 = 0ull, a1 = 0ull, b0 = 0ull, b1 = 0ull;
      if (half == 0) {
        STAGE_H(&g_x[0][0], 0, stA)     // x0 -> A (all 256)
        cpa_wait_group<0>();
        hbar(1);                        // x0 visible
        if (htid < 128) { CHUNK2(OFF_WBI, 0, OFF_BUFA) }
        else            { PRESCAN() }
        hbar(1);                        // x0 consumed
        STAGE_H(&g_x[0][0], 256, stA)   // x1 -> A
        cpa_wait_group<0>();
        hbar(1);                        // x1 visible
        if (htid < 128) { CHUNK2(OFF_WBI, 1, OFF_BUFA) }
      } else {
        cpa_wait_group<1>();            // h0,h1 done (SE may pend)
        hbar(2);                        // h visible
        if (htid < 128) {
          CHUNK2(OFF_WBH, 0, OFF_BUFB)
          CHUNK2(OFF_WBH, 1, OFF_BUFC)
          sCMB[frg * 8 + fdp]        = add2(a0, a1);
          sCMB[(frg + 16) * 8 + fdp] = add2(b0, b1);
        } else {
          PRESCAN()
        }
      }
      __syncthreads();
      if (tid < 128) {   // half0 FMA threads combine + write 2 rows
        unsigned long long axR0 = add2(a0, a1);
        unsigned long long axR1 = add2(b0, b1);
        unsigned long long ahR0 = sCMB[frg * 8 + fdp];
        unsigned long long ahR1 = sCMB[(frg + 16) * 8 + fdp];
        float x0v, x1v, h0v, h1v;
        float bi0 = SM[OFF_BIH + d0f], bi1 = SM[OFF_BIH + d0f + 1];
        float bh0 = SM[OFF_BHH + d0f], bh1 = SM[OFF_BHH + d0f + 1];
        asm("mov.b64 {%0, %1}, %2;" : "=f"(x0v), "=f"(x1v) : "l"(axR0));
        asm("mov.b64 {%0, %1}, %2;" : "=f"(h0v), "=f"(h1v) : "l"(ahR0));
        float2 r0;
        r0.x = tanhf(__fadd_rn(__fadd_rn(__fadd_rn(x0v, bi0), h0v), bh0));
        r0.y = tanhf(__fadd_rn(__fadd_rn(__fadd_rn(x1v, bi1), h1v), bh1));
        __stcg((float2*)&g_h[(t + 1) & 1][bc * 32 + frg][d0f], r0);
        asm("mov.b64 {%0, %1}, %2;" : "=f"(x0v), "=f"(x1v) : "l"(axR1));
        asm("mov.b64 {%0, %1}, %2;" : "=f"(h0v), "=f"(h1v) : "l"(ahR1));
        float2 r1;
        r1.x = tanhf(__fadd_rn(__fadd_rn(__fadd_rn(x0v, bi0), h0v), bh0));
        r1.y = tanhf(__fadd_rn(__fadd_rn(__fadd_rn(x1v, bi1), h1v), bh1));
        __stcg((float2*)&g_h[(t + 1) & 1][bc * 32 + frg + 16][d0f], r1);
      }
    }
    gbar(bc, epoch);

    // ============ Phase C: sampling (factored scores, fresh-16 + merge) ====
    {
      float* hb = SM + OFF_BUFA;            // [512]
      float* sE = SM + OFF_SE;

      cpa_wait_group<0>();                  // SE landed
      hb[tid] = __ldcg(&g_h[(t + 1) & 1][myb][tid]);
      __syncthreads();

      // dt + hmk partials: 1 elem/thread, dual warp reduce
      {
        float a  = __fmul_rn(hb[tid], SM[OFF_WTM + tid]);
        float m2 = __fmul_rn(hb[tid], SM[OFF_WMK + Ek + tid]);
        for (int o = 16; o; o >>= 1) {
          a  = __fadd_rn(a,  __shfl_down_sync(0xffffffffu, a, o));
          m2 += __shfl_down_sync(0xffffffffu, m2, o);
        }
        if (lane == 0) { red[warp] = a; red2[warp] = m2; }
      }
      __syncthreads();

      // neighbor scores: warp k does emb-part only (256), adds common h-part
      {
        const float* ev = sE + warp * 256;
        float acc0 = 0.0f, acc1 = 0.0f;
#pragma unroll
        for (int i = lane; i < Ek; i += 64) {
          acc0 = fmaf(ev[i], SM[OFF_WMK + i], acc0);
          acc1 = fmaf(ev[i + 32], SM[OFF_WMK + i + 32], acc1);
        }
        float acc = __fadd_rn(acc0, acc1);
        for (int o = 16; o; o >>= 1) acc += __shfl_down_sync(0xffffffffu, acc, o);
        if (lane == 0) {
          float hmk = red2[0];
          for (int w = 1; w < 16; w++) hmk = __fadd_rn(hmk, red2[w]);
          s_score[warp] = __fadd_rn(__fadd_rn(acc, hmk), SM[OFF_BT + 1]);
        }
      }
      __syncthreads();

      float newt = 0.0f;
      if (tid == 0) {
        float s = red[0];
        for (int w = 1; w < 16; w++) s = __fadd_rn(s, red[w]);
        float xx = __fadd_rn(s, SM[OFF_BT]);
        float sp = __fadd_rn(fmaxf(xx, 0.0f), log1pf(expf(-fabsf(xx))));
        newt = __fadd_rn(SM[OFF_BT + 2], sp);
      }

      // softmax + prob/cand updates + fresh-16 gumbel on warp 0
      if (warp == 0) {
        float sc = (lane < Kk) ? s_score[lane] : -3.4e38f;
        float mx = sc;
        for (int o = 8; o; o >>= 1)
          mx = fmaxf(mx, __shfl_xor_sync(0xffffffffu, mx, o));
        float ek = (lane < Kk) ? expf(__fadd_rn(sc, -mx)) : 0.0f;
        float ssum = 0.0f;
#pragma unroll
        for (int k = 0; k < Kk; k++)
          ssum = __fadd_rn(ssum, __shfl_sync(0xffffffffu, ek, k));
        float cp = sP[chosen];
        __syncwarp();
        float fv = -3.4e38f; int fi = 0x7fffffff;
        int base = 1 + t * (Kk - 1);
        if (lane < Kk) {
          float att = __fmul_rn(cp, __fdiv_rn(ek, ssum));
          int lf;
          if (lane == 0) {
            sP[chosen] = att;
            lf = chosen;
          } else {
            sP[base + lane - 1] = att;
            g_cand[myb][base + lane - 1] = s_neigh[lane];
            lf = base + lane - 1;
          }
          uint32_t ck0, ck1;
          tf2x32(0u, 42u, 0u, (uint32_t)t, ck0, ck1);
          fv = gumbel_val(att, ck0, ck1, (uint32_t)(myb * Lk + lf));
          fi = lf;
        }
        for (int o = 16; o; o >>= 1) {
          float ov = __shfl_down_sync(0xffffffffu, fv, o);
          int   oi = __shfl_down_sync(0xffffffffu, fi, o);
          if (ov > fv || (ov == fv && oi < fi)) { fv = ov; fi = oi; }
        }
        if (lane == 0) { redv[0] = fv; ri[0] = fi; }
      }
      __syncthreads();

      // merge fresh best with 8 prescan partials
      float bestv = redv[0]; int besti = ri[0];
#pragma unroll
      for (int s = 0; s < 8; s++) {
        float pv2 = redp[s]; int pi2 = ripre[s];
        if (pv2 > bestv || (pv2 == bestv && pi2 < besti)) {
          bestv = pv2; besti = pi2;
        }
      }
      chosen = besti;
      if (tid == 0) {
        int nm = g_cand[myb][besti];
        int col = t + 1;
        out[0 * 16384 + myb * Sk + col] = (float)nm;
        out[1 * 16384 + myb * Sk + col] = newt;
        out[2 * 16384 + myb * Sk + col] = (newt < 1000.0f) ? 1.0f : 0.0f;
        out[3 * 16384 + myb * Sk + col] = g_nrec[myb][besti];
        out[4 * 16384 + myb * Sk + col] = sP[besti];
        SM[OFF_BT + 2] = newt;
        __stcg(&g_last_m[myb], nm);
        __stcg(&g_last_t[myb], newt);
      }
    }
    gbar(bc, epoch);
  }
#undef STAGE_H
#undef CHUNK2
#undef PRESCAN
}

extern "C" void kernel_launch(void* const* d_in, const int* in_sizes, int n_in,
                              void* d_out, int out_size) {
  const int*   marker = (const int*)d_in[0];
  const float* timed  = (const float*)d_in[1];
  const float* maskd  = (const float*)d_in[2];
  const float* emb    = (const float*)d_in[3];
  const int*   nlist  = (const int*)d_in[4];
  const float* nprob  = (const float*)d_in[5];
  const float* W_te   = (const float*)d_in[6];
  const float* b_te   = (const float*)d_in[7];
  const float* W_el   = (const float*)d_in[8];
  const float* b_el   = (const float*)d_in[9];
  const float* W_ih   = (const float*)d_in[10];
  const float* b_ih   = (const float*)d_in[11];
  const float* W_hh   = (const float*)d_in[12];
  const float* b_hh   = (const float*)d_in[13];
  const float* W_time = (const float*)d_in[14];
  const float* b_time = (const float*)d_in[15];
  const float* W_mk   = (const float*)d_in[16];
  const float* b_mk   = (const float*)d_in[17];
  float* out = (float*)d_out;

  cudaFuncSetAttribute(rnn_persistent,
                       cudaFuncAttributeMaxDynamicSharedMemorySize, SM_BYTES);
  reset_kernel<<<1, 128>>>();
  rnn_persistent<<<148, 512, SM_BYTES>>>(marker, timed, maskd, emb, nlist, nprob,
                                         W_te, b_te, W_el, b_el, W_ih, b_ih,
                                         W_hh, b_hh, W_time, b_time, W_mk, b_mk,
                                         out);
}